// round 15
// baseline (speedup 1.0000x reference)
#include <cuda_runtime.h>
#include <cuda_bf16.h>
#include <math.h>
#include <stdint.h>

#define NTOK   32768
#define BATCH  4
#define CIN    256
#define OC3    384
#define HID    128
#define NHEAD  4
#define DHEAD  32
#define SCALE  0.17677669529663687f   // 32^-0.5
#define LN_EPS 1e-5f

// ---------------- scratch (static device globals; no allocation) ----------------
__device__ __align__(16) float g_qkv[(size_t)BATCH * OC3 * NTOK];   // 201 MB
__device__ __align__(16) float g_kmax[BATCH * NHEAD * DHEAD];
__device__ __align__(16) float g_krinv[BATCH * NHEAD * DHEAD];
__device__ __align__(16) float g_ctx[BATCH * NHEAD * DHEAD * DHEAD];
__device__ __align__(16) float2 g_kpart[512 * 256];                 // 1 MB partials
// W_qkv split planes: [plane(hi,lo)][mt(3)][chunk(4)][m(128)][k(64)] bf16
__device__ __align__(16) __nv_bfloat16 g_w[2 * 3 * 4 * 128 * 64];   // 768 KB
// W_out split planes: [plane(hi,lo)][o(256)][c(128)] bf16
__device__ __align__(16) __nv_bfloat16 g_w2[2 * 256 * 128];         // 128 KB

// ========================= helpers =========================
__device__ __forceinline__ uint32_t smem_u32(const void* p) {
    uint32_t a;
    asm("{ .reg .u64 t; cvta.to.shared.u64 t, %1; cvt.u32.u64 %0, t; }"
        : "=r"(a) : "l"(p));
    return a;
}

#define CP_ASYNC16(dst, src) \
    asm volatile("cp.async.cg.shared.global [%0], [%1], 16;" :: "r"(dst), "l"(src) : "memory")
#define CP_COMMIT() asm volatile("cp.async.commit_group;" ::: "memory")
#define CP_WAIT0()  asm volatile("cp.async.wait_group 0;" ::: "memory")

#define LDSM_X4(r0, r1, r2, r3, addr) \
    asm volatile("ldmatrix.sync.aligned.m8n8.x4.shared.b16 {%0,%1,%2,%3}, [%4];" \
                 : "=r"(r0), "=r"(r1), "=r"(r2), "=r"(r3) : "r"(addr))
#define LDSM_X4_T(r0, r1, r2, r3, addr) \
    asm volatile("ldmatrix.sync.aligned.m8n8.x4.trans.shared.b16 {%0,%1,%2,%3}, [%4];" \
                 : "=r"(r0), "=r"(r1), "=r"(r2), "=r"(r3) : "r"(addr))

#define MMA_16816(c, a, b0, b1) \
    asm volatile("mma.sync.aligned.m16n8k16.row.col.f32.bf16.bf16.f32 " \
                 "{%0,%1,%2,%3}, {%4,%5,%6,%7}, {%8,%9}, {%0,%1,%2,%3};" \
                 : "+f"((c)[0]), "+f"((c)[1]), "+f"((c)[2]), "+f"((c)[3]) \
                 : "r"((a)[0]), "r"((a)[1]), "r"((a)[2]), "r"((a)[3]), "r"(b0), "r"(b1))

__device__ __forceinline__ void bf16_split(float v, __nv_bfloat16& hi, __nv_bfloat16& lo) {
    hi = __float2bfloat16(v);
    lo = __float2bfloat16(v - __bfloat162float(hi));
}

// ========================= W pre-split kernels (tiny) =========================
__global__ __launch_bounds__(512) void k_wconv(const float* __restrict__ w) {
    int idx = blockIdx.x * 512 + threadIdx.x;     // o*256 + c
    if (idx >= OC3 * CIN) return;
    int o = idx >> 8, c = idx & 255;
    __nv_bfloat16 hi, lo;
    bf16_split(w[idx], hi, lo);
    int mt = o >> 7, m = o & 127, ch = c >> 6, k = c & 63;
    size_t base = ((size_t)((mt * 4 + ch)) * 128 + m) * 64 + k;
    g_w[base]                            = hi;
    g_w[(size_t)3 * 4 * 128 * 64 + base] = lo;
}

__global__ __launch_bounds__(512) void k_wconv2(const float* __restrict__ w) {
    int idx = blockIdx.x * 512 + threadIdx.x;     // o*128 + c
    if (idx >= CIN * HID) return;
    __nv_bfloat16 hi, lo;
    bf16_split(w[idx], hi, lo);
    g_w2[idx]              = hi;
    g_w2[CIN * HID + idx]  = lo;
}

__global__ void k_zero_ctx() {
    g_ctx[blockIdx.x * 1024 + threadIdx.x] = 0.f;
}

// ========================= QKV GEMM on mma.sync (HMMA) =========================
// 128 threads, 4 warps (2m x 2n), warp tile 64x64, CTA tile 128m x 128n.
// 2 CTAs/SM. R10/R13 structure + fused k-softmax partials in epilogue (mt==1).
#define QKV_SMEM 98304
#define QB_OFF   32768

__global__ __launch_bounds__(128, 2) void k_qkv_mma(const float* __restrict__ x) {
    extern __shared__ __align__(1024) char smem[];
    const uint32_t sb = smem_u32(smem);
    const int mt = blockIdx.x;            // mt adjacent -> X slice L2 reuse
    const int n0 = blockIdx.y * 128;
    const int b  = blockIdx.z;
    const int tid = threadIdx.x, wid = tid >> 5, lane = tid & 31;
    const int warp_m = wid >> 1, warp_n = wid & 1;
    const float* xb = x + (size_t)b * CIN * NTOK + n0;

    float acc[4][8][4];
#pragma unroll
    for (int i = 0; i < 4; i++)
#pragma unroll
        for (int j = 0; j < 8; j++)
#pragma unroll
            for (int r = 0; r < 4; r++) acc[i][j][r] = 0.f;

#define WCP(c) do { \
    _Pragma("unroll") \
    for (int p = 0; p < 2; p++) { \
        const char* srcb = (const char*)g_w + (((size_t)(p * 3 + mt) * 4 + (c))) * 16384; \
        _Pragma("unroll") \
        for (int i = 0; i < 8; i++) { \
            int u = tid + 128 * i;               /* 0..1023 16B units */ \
            int m = u >> 3, ks = u & 7; \
            uint32_t dst = sb + p * 16384 + m * 128 + ((ks * 16) ^ ((m & 7) << 4)); \
            CP_ASYNC16(dst, srcb + (size_t)u * 16); \
        } \
    } \
} while (0)

    float4 xr[8];
#define XLDG(c, hh) do { \
    _Pragma("unroll") \
    for (int i = 0; i < 8; i++) { \
        int r = (hh) * 32 + (tid >> 5) + 4 * i; \
        xr[i] = *(const float4*)&xb[(size_t)((c) * 64 + r) * NTOK + (tid & 31) * 4]; \
    } \
} while (0)

#define XSTS(buf, hh) do { \
    _Pragma("unroll") \
    for (int i = 0; i < 8; i++) { \
        int r = (hh) * 32 + (tid >> 5) + 4 * i; \
        float4 v = xr[i]; \
        __nv_bfloat16 h0, h1, h2, h3, l0, l1, l2, l3; \
        bf16_split(v.x, h0, l0); bf16_split(v.y, h1, l1); \
        bf16_split(v.z, h2, l2); bf16_split(v.w, h3, l3); \
        uint2 hv = make_uint2((uint32_t)__bfloat16_as_ushort(h0) | ((uint32_t)__bfloat16_as_ushort(h1) << 16), \
                              (uint32_t)__bfloat16_as_ushort(h2) | ((uint32_t)__bfloat16_as_ushort(h3) << 16)); \
        uint2 lv = make_uint2((uint32_t)__bfloat16_as_ushort(l0) | ((uint32_t)__bfloat16_as_ushort(l1) << 16), \
                              (uint32_t)__bfloat16_as_ushort(l2) | ((uint32_t)__bfloat16_as_ushort(l3) << 16)); \
        uint32_t off = (uint32_t)r * 256 + ((((uint32_t)(tid & 31)) * 8) ^ (((uint32_t)r & 7) << 4)); \
        *(uint2*)(smem + QB_OFF + (buf) * 32768 + off)         = hv; \
        *(uint2*)(smem + QB_OFF + (buf) * 32768 + 16384 + off) = lv; \
    } \
} while (0)

    const int lm = lane & 15;
    const int khalf = (lane >> 4) << 3;

#define MMATERM(pa, pb, cur) do { \
    const uint32_t abase = sb + (pa) * 16384; \
    const uint32_t bbase = sb + QB_OFF + (cur) * 32768 + (pb) * 16384; \
    _Pragma("unroll") \
    for (int ks = 0; ks < 4; ks++) { \
        uint32_t ar[4][4]; \
        _Pragma("unroll") \
        for (int im = 0; im < 4; im++) { \
            uint32_t m_row = (uint32_t)(warp_m * 64 + im * 16 + lm); \
            uint32_t k_off = (uint32_t)(ks * 16 + khalf); \
            uint32_t addr = abase + m_row * 128 + ((k_off * 2) ^ ((m_row & 7) << 4)); \
            LDSM_X4(ar[im][0], ar[im][1], ar[im][2], ar[im][3], addr); \
        } \
        uint32_t br[4][4]; \
        _Pragma("unroll") \
        for (int jb = 0; jb < 4; jb++) { \
            uint32_t k_row = (uint32_t)(ks * 16 + lm); \
            uint32_t n_off = (uint32_t)(warp_n * 64 + jb * 16 + khalf); \
            uint32_t addr = bbase + k_row * 256 + ((n_off * 2) ^ ((k_row & 7) << 4)); \
            LDSM_X4_T(br[jb][0], br[jb][1], br[jb][2], br[jb][3], addr); \
        } \
        _Pragma("unroll") \
        for (int im = 0; im < 4; im++) { \
            _Pragma("unroll") \
            for (int jb = 0; jb < 4; jb++) { \
                MMA_16816(acc[im][jb * 2 + 0], ar[im], br[jb][0], br[jb][1]); \
                MMA_16816(acc[im][jb * 2 + 1], ar[im], br[jb][2], br[jb][3]); \
            } \
        } \
    } \
} while (0)

    // prologue: chunk 0 (W + both B halves)
    WCP(0);
    CP_COMMIT();
    XLDG(0, 0);
    XSTS(0, 0);
    XLDG(0, 1);
    XSTS(0, 1);
    CP_WAIT0();
    __syncthreads();

    for (int c = 0; c < 4; ++c) {
        const int cur = c & 1, nxt = cur ^ 1;
        if (c < 3) XLDG(c + 1, 0);

        MMATERM(0, 0, cur);          // Ahi x Bhi
        if (c < 3) {
            XSTS(nxt, 0);
            XLDG(c + 1, 1);
        }
        MMATERM(0, 1, cur);          // Ahi x Blo
        MMATERM(1, 0, cur);          // Alo x Bhi  (last A read this chunk)

        __syncthreads();             // all warps done reading A
        if (c < 3) {
            WCP(c + 1);              // overwrite single A buffer
            CP_COMMIT();
            XSTS(nxt, 1);
            CP_WAIT0();
        }
        __syncthreads();
    }

    // ---- epilogue: direct STG ----
    const int g = lane >> 2, tig = lane & 3;
    float* outb = g_qkv + ((size_t)b * OC3 + mt * 128) * NTOK + n0;
#pragma unroll
    for (int im = 0; im < 4; im++) {
        const int row = warp_m * 64 + im * 16 + g;
#pragma unroll
        for (int jg = 0; jg < 8; jg++) {
            const int col = warp_n * 64 + jg * 8 + tig * 2;
            *(float2*)&outb[(size_t)row * NTOK + col] =
                make_float2(acc[im][jg][0], acc[im][jg][1]);
            *(float2*)&outb[(size_t)(row + 8) * NTOK + col] =
                make_float2(acc[im][jg][2], acc[im][jg][3]);
        }
    }

    // ---- fused k-softmax partials (K rows live in mt==1 CTAs) ----
    if (mt == 1) {
        float rm[8], rs[8];
#pragma unroll
        for (int im = 0; im < 4; im++) {
#pragma unroll
            for (int hf = 0; hf < 2; hf++) {
                float m = -1e30f;
#pragma unroll
                for (int jg = 0; jg < 8; jg++)
                    m = fmaxf(m, fmaxf(acc[im][jg][hf * 2 + 0], acc[im][jg][hf * 2 + 1]));
                float s = 0.f;
#pragma unroll
                for (int jg = 0; jg < 8; jg++)
                    s += __expf(acc[im][jg][hf * 2 + 0] - m) +
                         __expf(acc[im][jg][hf * 2 + 1] - m);
                // reduce over the 4 tig lanes (same rows)
#pragma unroll
                for (int d = 1; d < 4; d <<= 1) {
                    float mo = __shfl_xor_sync(0xffffffffu, m, d);
                    float so = __shfl_xor_sync(0xffffffffu, s, d);
                    float M = fmaxf(m, mo);
                    s = s * __expf(m - M) + so * __expf(mo - M);
                    m = M;
                }
                rm[im * 2 + hf] = m;
                rs[im * 2 + hf] = s;
            }
        }
        float* pm = (float*)(smem + QB_OFF);      // B region dead; reuse
        float* ps = pm + 128;
        __syncthreads();
        if (warp_n == 0 && tig == 0) {
#pragma unroll
            for (int im = 0; im < 4; im++) {
                int r0 = warp_m * 64 + im * 16 + g;
                pm[r0]     = rm[im * 2];     ps[r0]     = rs[im * 2];
                pm[r0 + 8] = rm[im * 2 + 1]; ps[r0 + 8] = rs[im * 2 + 1];
            }
        }
        __syncthreads();
        if (warp_n == 1 && tig == 0) {
#pragma unroll
            for (int im = 0; im < 4; im++) {
#pragma unroll
                for (int hf = 0; hf < 2; hf++) {
                    int r0 = warp_m * 64 + im * 16 + g + hf * 8;
                    float m1 = pm[r0], s1 = ps[r0];
                    float m2 = rm[im * 2 + hf], s2 = rs[im * 2 + hf];
                    float M = fmaxf(m1, m2);
                    float S = s1 * __expf(m1 - M) + s2 * __expf(m2 - M);
                    g_kpart[(size_t)(b * 128 + r0) * 256 + blockIdx.y] = make_float2(M, S);
                }
            }
        }
    }
#undef WCP
#undef XLDG
#undef XSTS
#undef MMATERM
}

// =====================================================================
// Kernel 2: combine 256 per-tile (max, sumexp) partials per K row.
// =====================================================================
__global__ __launch_bounds__(256) void k_kcomb() {
    const int row = blockIdx.x;          // 0..511
    const int tid = threadIdx.x;
    __shared__ float sm[8], ss[8];
    float2 v = g_kpart[(size_t)row * 256 + tid];
    float m = v.x, s = v.y;
#pragma unroll
    for (int d = 16; d > 0; d >>= 1) {
        float mo = __shfl_xor_sync(0xffffffffu, m, d);
        float so = __shfl_xor_sync(0xffffffffu, s, d);
        float M = fmaxf(m, mo);
        s = s * __expf(m - M) + so * __expf(mo - M);
        m = M;
    }
    if ((tid & 31) == 0) { sm[tid >> 5] = m; ss[tid >> 5] = s; }
    __syncthreads();
    if (tid < 8) {
        m = sm[tid]; s = ss[tid];
#pragma unroll
        for (int d = 4; d > 0; d >>= 1) {
            float mo = __shfl_xor_sync(0x000000ffu, m, d);
            float so = __shfl_xor_sync(0x000000ffu, s, d);
            float M = fmaxf(m, mo);
            s = s * __expf(m - M) + so * __expf(mo - M);
            m = M;
        }
        if (tid == 0) {
            g_kmax[row]  = m;
            g_krinv[row] = 1.f / s;
        }
    }
}

// =====================================================================
// Kernel 3: context[b,h,d,e] = sum_n softmax_k(d,n) * v(e,n)
// split-K: 32 chunks of 1024 tokens. Token-major (transposed) staging
// with XOR swizzle -> float4 broadcast LDS in the inner loop.
// =====================================================================
__global__ __launch_bounds__(256) void k_context() {
    const int chunk = blockIdx.x;
    const int h = blockIdx.y, b = blockIdx.z;
    const int tid = threadIdx.x;
    const int g = tid >> 6, t = tid & 63;
    const int d0 = (t >> 3) << 2;
    const int e0 = (t & 7) << 2;

    __shared__ float skt[64 * 36];   // [token][d^swz], pad 36
    __shared__ float svt[64 * 36];   // [token][e^swz]

    const int lr1 = tid >> 4;              // d row 0..15
    const int c4  = (tid & 15) << 2;       // token 0..60
    const int krow = (b * NHEAD + h) * DHEAD;
    const float km1 = g_kmax[krow + lr1],      ri1 = g_krinv[krow + lr1];
    const float km2 = g_kmax[krow + lr1 + 16], ri2 = g_krinv[krow + lr1 + 16];

    const float* kp = g_qkv + ((size_t)(b * OC3 + HID      + h * DHEAD)) * NTOK;
    const float* vp = g_qkv + ((size_t)(b * OC3 + 2 * HID  + h * DHEAD)) * NTOK;

    float acc[4][4];
#pragma unroll
    for (int i = 0; i < 4; i++)
#pragma unroll
        for (int j = 0; j < 4; j++) acc[i][j] = 0.f;

    const int nchunk0 = chunk * 1024;
    for (int it = 0; it < 16; it++) {
        const int nb = nchunk0 + it * 64;
        float4 kv1 = *(const float4*)&kp[(size_t)lr1 * NTOK + nb + c4];
        float4 kv2 = *(const float4*)&kp[(size_t)(lr1 + 16) * NTOK + nb + c4];
        float4 vv1 = *(const float4*)&vp[(size_t)lr1 * NTOK + nb + c4];
        float4 vv2 = *(const float4*)&vp[(size_t)(lr1 + 16) * NTOK + nb + c4];
        float k1[4] = {kv1.x, kv1.y, kv1.z, kv1.w};
        float k2[4] = {kv2.x, kv2.y, kv2.z, kv2.w};
        float v1[4] = {vv1.x, vv1.y, vv1.z, vv1.w};
        float v2[4] = {vv2.x, vv2.y, vv2.z, vv2.w};
#pragma unroll
        for (int j = 0; j < 4; j++) {
            const int tok = c4 + j;
            const int sw = (tok & 7) << 2;
            skt[tok * 36 + (lr1 ^ sw)]        = __expf(k1[j] - km1) * ri1;
            skt[tok * 36 + ((lr1 + 16) ^ sw)] = __expf(k2[j] - km2) * ri2;
            svt[tok * 36 + (lr1 ^ sw)]        = v1[j];
            svt[tok * 36 + ((lr1 + 16) ^ sw)] = v2[j];
        }
        __syncthreads();

        const int nnb = g << 4;
#pragma unroll
        for (int s = 0; s < 16; s++) {
            const int nn = nnb + s;
            const int sw = (nn & 7) << 2;
            float4 ka4 = *(const float4*)&skt[nn * 36 + (d0 ^ sw)];
            float4 vb4 = *(const float4*)&svt[nn * 36 + (e0 ^ sw)];
            float ka[4] = {ka4.x, ka4.y, ka4.z, ka4.w};
            float vb[4] = {vb4.x, vb4.y, vb4.z, vb4.w};
#pragma unroll
            for (int i = 0; i < 4; i++)
#pragma unroll
                for (int j = 0; j < 4; j++) acc[i][j] += ka[i] * vb[j];
        }
        __syncthreads();
    }

    float* cp = g_ctx + (size_t)(b * NHEAD + h) * DHEAD * DHEAD;
#pragma unroll
    for (int i = 0; i < 4; i++)
#pragma unroll
        for (int j = 0; j < 4; j++)
            atomicAdd(&cp[(d0 + i) * DHEAD + e0 + j], acc[i][j]);
}

// =====================================================================
// Kernel 4 (fused): q-softmax + att + w_out GEMM (HMMA) + bias + LN.
// EXACT R13 structure: 256 threads, warp tile 64x64, CTA 256 oc x 128 tok.
// =====================================================================
#define FIN_SMEM   219136
#define F_OFF_B    65536
#define F_OFF_QS   131072
#define F_OFF_CTX  198656
#define F_OFF_BIAS 215040
#define F_OFF_GAM  216064
#define F_OFF_BET  217088
#define F_OFF_MEAN 218112
#define F_OFF_STD  218624

__global__ __launch_bounds__(256, 1) void k_final2(const float* __restrict__ bias,
                                                   const float* __restrict__ gamma,
                                                   const float* __restrict__ beta,
                                                   float* __restrict__ out) {
    extern __shared__ __align__(1024) char smem[];
    const uint32_t sb = smem_u32(smem);
    const int b  = blockIdx.y;
    const int n0 = blockIdx.x * 128;
    const int tid = threadIdx.x, wid = tid >> 5, lane = tid & 31;
    const int warp_m = wid >> 1, warp_n = wid & 1;

    float* qs    = (float*)(smem + F_OFF_QS);    // [128][132]
    float* sctx  = (float*)(smem + F_OFF_CTX);   // [4096]
    float* sbias = (float*)(smem + F_OFF_BIAS);
    float* sgam  = (float*)(smem + F_OFF_GAM);
    float* sbet  = (float*)(smem + F_OFF_BET);
    float* smean = (float*)(smem + F_OFF_MEAN);
    float* srstd = (float*)(smem + F_OFF_STD);

#define WCP2(p) do { \
    const char* srcb = (const char*)g_w2 + (size_t)(p) * 65536; \
    _Pragma("unroll") \
    for (int i = 0; i < 16; i++) { \
        int u = tid + 256 * i; \
        int m = u >> 4, ks = u & 15; \
        uint32_t dst = sb + m * 256 + ((ks * 16) ^ ((m & 7) << 4)); \
        CP_ASYNC16(dst, srcb + (size_t)u * 16); \
    } \
} while (0)

    // ---- 1. async copy: w_out HI plane + ctx + q tile (all overlapped) ----
    WCP2(0);
    {
        const char* csrc = (const char*)(g_ctx + b * 4096);
#pragma unroll
        for (int i = 0; i < 4; i++) {
            int u = tid + 256 * i;               // 0..1023 16B units
            CP_ASYNC16(sb + F_OFF_CTX + u * 16, csrc + (size_t)u * 16);
        }
#pragma unroll
        for (int i = 0; i < 16; i++) {
            int idx = tid + i * 256;             // 0..4095 float4s (128 rows x 32)
            int r = idx >> 5, c4 = (idx & 31) << 2;
            CP_ASYNC16(sb + F_OFF_QS + (uint32_t)(r * 132 + c4) * 4,
                       (const char*)&g_qkv[((size_t)b * OC3 + r) * NTOK + n0 + c4]);
        }
    }
    CP_COMMIT();

    // ---- 2. LN params (small, plain LDG) ----
    if (tid < 64) {
        sbias[tid]       = bias[tid];        sbias[tid + 64]  = bias[tid + 64];
        sbias[tid + 128] = bias[tid + 128];  sbias[tid + 192] = bias[tid + 192];
        sgam[tid]        = gamma[tid];       sgam[tid + 64]   = gamma[tid + 64];
        sgam[tid + 128]  = gamma[tid + 128]; sgam[tid + 192]  = gamma[tid + 192];
        sbet[tid]        = beta[tid];        sbet[tid + 64]   = beta[tid + 64];
        sbet[tid + 128]  = beta[tid + 128];  sbet[tid + 192]  = beta[tid + 192];
    }
    CP_WAIT0();
    __syncthreads();

    // ---- 3. q softmax over d per (h, n): 512 pairs, 2 per thread ----
#pragma unroll
    for (int pp = 0; pp < 2; pp++) {
        const int p = tid + pp * 256;
        const int h = p >> 7, n = p & 127;
        float qv[32];
        float m = -1e30f;
#pragma unroll
        for (int d = 0; d < 32; d++) { qv[d] = qs[(h * 32 + d) * 132 + n]; m = fmaxf(m, qv[d]); }
        float s = 0.f;
#pragma unroll
        for (int d = 0; d < 32; d++) { qv[d] = __expf(qv[d] - m); s += qv[d]; }
        const float r = SCALE / s;
#pragma unroll
        for (int d = 0; d < 32; d++) qs[(h * 32 + d) * 132 + n] = qv[d] * r;
    }
    __syncthreads();

    // ---- 4. att[e, n] = sum_d ctx[h,d,e] * qs[h*32+d][n] (tiled, float4 LDS) ----
    {
        const int e = tid >> 1, nh = tid & 1;    // e 0..127
        const int h = e >> 5, ep = e & 31;
        const float* cb = sctx + h * 1024 + ep;
        char* bhi = smem + F_OFF_B;
        char* blo = bhi + 32768;
#pragma unroll
        for (int half = 0; half < 2; half++) {
            float av[32];
#pragma unroll
            for (int j = 0; j < 32; j++) av[j] = 0.f;
            const float* qb = qs + (h * 32) * 132 + nh * 64 + half * 32;
#pragma unroll
            for (int d = 0; d < 32; d++) {
                const float cv = cb[d * 32];
                const float4* q4 = (const float4*)(qb + d * 132);
#pragma unroll
                for (int j4 = 0; j4 < 8; j4++) {
                    float4 q = q4[j4];
                    av[j4 * 4 + 0] += cv * q.x;
                    av[j4 * 4 + 1] += cv * q.y;
                    av[j4 * 4 + 2] += cv * q.z;
                    av[j4 * 4 + 3] += cv * q.w;
                }
            }
#pragma unroll
            for (int t = 0; t < 16; t++) {
                __nv_bfloat16 h0, h1, l0, l1;
                bf16_split(av[2 * t],     h0, l0);
                bf16_split(av[2 * t + 1], h1, l1);
                uint32_t hv = (uint32_t)__bfloat16_as_ushort(h0) | ((uint32_t)__bfloat16_as_ushort(h1) << 16);
                uint32_t lv = (uint32_t)__bfloat16_as_ushort(l0) | ((uint32_t)__bfloat16_as_ushort(l1) << 16);
                uint32_t off = (uint32_t)e * 256 +
                    (((uint32_t)(nh * 128 + half * 64 + 4 * t)) ^ (((uint32_t)e & 7) << 4));
                *(uint32_t*)(bhi + off) = hv;
                *(uint32_t*)(blo + off) = lv;
            }
        }
    }
    __syncthreads();

    // ---- 5. MMA: staged A. (Ahi,Bhi), (Ahi,Blo), then Alo, (Alo,Bhi) ----
    float acc[4][8][4];
#pragma unroll
    for (int i = 0; i < 4; i++)
#pragma unroll
        for (int j = 0; j < 8; j++)
#pragma unroll
            for (int r = 0; r < 4; r++) acc[i][j][r] = 0.f;

    const int lm = lane & 15;
    const int khalf = (lane >> 4) << 3;

#define FTERM(pb) do { \
    const uint32_t bbase = sb + F_OFF_B + (pb) * 32768; \
    _Pragma("unroll") \
    for (int ks = 0; ks < 8; ks++) { \
        uint32_t ar[4][4]; \
        _Pragma("unroll") \
        for (int im = 0; im < 4; im++) { \
            uint32_t m_row = (uint32_t)(warp_m * 64 + im * 16 + lm); \
            uint32_t k_off = (uint32_t)(ks * 16 + khalf); \
            uint32_t addr = sb + m_row * 256 + ((k_off * 2) ^ ((m_row & 7) << 4)); \
            LDSM_X4(ar[im][0], ar[im][1], ar[im][2], ar[im][3], addr); \
        } \
        uint32_t br[4][4]; \
        _Pragma("unroll") \
        for (int jb = 0; jb < 4; jb++) { \
            uint32_t k_row = (uint32_t)(ks * 16 + lm); \
            uint32_t n_off = (uint32_t)(warp_n * 64 + jb * 16 + khalf); \
            uint32_t addr = bbase + k_row * 256 + ((n_off * 2) ^ ((k_row & 7) << 4)); \
            LDSM_X4_T(br[jb][0], br[jb][1], br[jb][2], br[jb][3], addr); \
        } \
        _Pragma("unroll") \
        for (int im = 0; im < 4; im++) { \
            _Pragma("unroll") \
            for (int jb = 0; jb < 4; jb++) { \
                MMA_16816(acc[im][jb * 2 + 0], ar[im], br[jb][0], br[jb][1]); \
                MMA_16816(acc[im][jb * 2 + 1], ar[im], br[jb][2], br[jb][3]); \
            } \
        } \
    } \
} while (0)

    FTERM(0);           // Ahi x Bhi
    FTERM(1);           // Ahi x Blo
    __syncthreads();    // all warps done reading Ahi
    WCP2(1);            // overwrite A with LO plane
    CP_COMMIT();
    CP_WAIT0();
    __syncthreads();
    FTERM(0);           // Alo x Bhi
    __syncthreads();    // A/B/qs regions dead; reuse as stage

    // ---- 6. stage[256][132] = acc + bias ----
    float* stage = (float*)smem;
    {
        const int g = lane >> 2, tig = lane & 3;
#pragma unroll
        for (int im = 0; im < 4; im++) {
            const int row = warp_m * 64 + im * 16 + g;
            const float b0 = sbias[row], b1 = sbias[row + 8];
#pragma unroll
            for (int jg = 0; jg < 8; jg++) {
                const int col = warp_n * 64 + jg * 8 + tig * 2;
                *(float2*)&stage[row * 132 + col] =
                    make_float2(acc[im][jg][0] + b0, acc[im][jg][1] + b0);
                *(float2*)&stage[(row + 8) * 132 + col] =
                    make_float2(acc[im][jg][2] + b1, acc[im][jg][3] + b1);
            }
        }
    }
    __syncthreads();

    // ---- 7. LN stats: 2 threads per token ----
    {
        const int t = tid >> 1, part = tid & 1;
        float sum = 0.f, sq = 0.f;
#pragma unroll
        for (int jj = 0; jj < 128; jj++) {
            const float v = stage[(part + jj * 2) * 132 + t];
            sum += v; sq += v * v;
        }
        sum += __shfl_xor_sync(0xffffffffu, sum, 1);
        sq  += __shfl_xor_sync(0xffffffffu, sq, 1);
        const float mean = sum * (1.f / 256.f);
        const float var  = sq * (1.f / 256.f) - mean * mean;
        if (part == 0) {
            smean[t] = mean;
            srstd[t] = rsqrtf(var + LN_EPS);
        }
    }
    __syncthreads();

    // ---- 8. normalized write-out (8192 float4s) ----
    float* outb = out + (size_t)b * CIN * NTOK + n0;
#pragma unroll
    for (int it = 0; it < 32; it++) {
        int idx = it * 256 + tid;
        int o = idx >> 5, q = (idx & 31) << 2;
        const float gm = sgam[o], bt = sbet[o];
        float4 v = *(float4*)&stage[o * 132 + q];
        v.x = (v.x - smean[q + 0]) * srstd[q + 0] * gm + bt;
        v.y = (v.y - smean[q + 1]) * srstd[q + 1] * gm + bt;
        v.z = (v.z - smean[q + 2]) * srstd[q + 2] * gm + bt;
        v.w = (v.w - smean[q + 3]) * srstd[q + 3] * gm + bt;
        *(float4*)&outb[(size_t)o * NTOK + q] = v;
    }
#undef WCP2
#undef FTERM
}

// =====================================================================
extern "C" void kernel_launch(void* const* d_in, const int* in_sizes, int n_in,
                              void* d_out, int out_size) {
    const float* x      = (const float*)d_in[0];
    const float* w_qkv  = (const float*)d_in[1];
    const float* w_out  = (const float*)d_in[2];
    const float* bias   = (const float*)d_in[3];
    const float* gamma  = (const float*)d_in[4];
    const float* beta   = (const float*)d_in[5];
    float* out = (float*)d_out;

    cudaFuncSetAttribute(k_qkv_mma, cudaFuncAttributeMaxDynamicSharedMemorySize,
                         QKV_SMEM);
    cudaFuncSetAttribute(k_final2, cudaFuncAttributeMaxDynamicSharedMemorySize,
                         FIN_SMEM);

    // k_qkv_mma stays at launch index 3 (the one ncu profiles).
    k_wconv<<<192, 512>>>(w_qkv);                                   // 0
    k_wconv2<<<64, 512>>>(w_out);                                   // 1
    k_zero_ctx<<<16, 1024>>>();                                     // 2
    k_qkv_mma<<<dim3(3, NTOK / 128, BATCH), 128, QKV_SMEM>>>(x);    // 3 <- profiled
    k_kcomb<<<512, 256>>>();                                        // 4 (replaces kstats)
    k_context<<<dim3(32, NHEAD, BATCH), 256>>>();                   // 5
    k_final2<<<dim3(NTOK / 128, BATCH), 256, FIN_SMEM>>>(bias, gamma, beta, out); // 6
}

// round 16
// speedup vs baseline: 1.1933x; 1.1933x over previous
#include <cuda_runtime.h>
#include <cuda_bf16.h>
#include <math.h>
#include <stdint.h>

#define NTOK   32768
#define BATCH  4
#define CIN    256
#define OC3    384
#define HID    128
#define NHEAD  4
#define DHEAD  32
#define SCALE  0.17677669529663687f   // 32^-0.5
#define LN_EPS 1e-5f

// ---------------- scratch (static device globals; no allocation) ----------------
__device__ __align__(16) float g_qkv[(size_t)BATCH * OC3 * NTOK];   // 201 MB
__device__ __align__(16) float g_kmax[BATCH * NHEAD * DHEAD];
__device__ __align__(16) float g_krinv[BATCH * NHEAD * DHEAD];
__device__ __align__(16) float g_ctx[BATCH * NHEAD * DHEAD * DHEAD];
__device__ __align__(16) float2 g_kpart[512 * 256];                 // 1 MB partials
// W_qkv split planes: [plane(hi,lo)][mt(3)][chunk(4)][m(128)][k(64)] bf16
__device__ __align__(16) __nv_bfloat16 g_w[2 * 3 * 4 * 128 * 64];   // 768 KB
// W_out split planes: [plane(hi,lo)][o(256)][c(128)] bf16
__device__ __align__(16) __nv_bfloat16 g_w2[2 * 256 * 128];         // 128 KB

// ========================= helpers =========================
__device__ __forceinline__ uint32_t smem_u32(const void* p) {
    uint32_t a;
    asm("{ .reg .u64 t; cvta.to.shared.u64 t, %1; cvt.u32.u64 %0, t; }"
        : "=r"(a) : "l"(p));
    return a;
}

#define CP_ASYNC16(dst, src) \
    asm volatile("cp.async.cg.shared.global [%0], [%1], 16;" :: "r"(dst), "l"(src) : "memory")
#define CP_COMMIT() asm volatile("cp.async.commit_group;" ::: "memory")
#define CP_WAIT0()  asm volatile("cp.async.wait_group 0;" ::: "memory")

#define LDSM_X4(r0, r1, r2, r3, addr) \
    asm volatile("ldmatrix.sync.aligned.m8n8.x4.shared.b16 {%0,%1,%2,%3}, [%4];" \
                 : "=r"(r0), "=r"(r1), "=r"(r2), "=r"(r3) : "r"(addr))
#define LDSM_X4_T(r0, r1, r2, r3, addr) \
    asm volatile("ldmatrix.sync.aligned.m8n8.x4.trans.shared.b16 {%0,%1,%2,%3}, [%4];" \
                 : "=r"(r0), "=r"(r1), "=r"(r2), "=r"(r3) : "r"(addr))

#define MMA_16816(c, a, b0, b1) \
    asm volatile("mma.sync.aligned.m16n8k16.row.col.f32.bf16.bf16.f32 " \
                 "{%0,%1,%2,%3}, {%4,%5,%6,%7}, {%8,%9}, {%0,%1,%2,%3};" \
                 : "+f"((c)[0]), "+f"((c)[1]), "+f"((c)[2]), "+f"((c)[3]) \
                 : "r"((a)[0]), "r"((a)[1]), "r"((a)[2]), "r"((a)[3]), "r"(b0), "r"(b1))

__device__ __forceinline__ void bf16_split(float v, __nv_bfloat16& hi, __nv_bfloat16& lo) {
    hi = __float2bfloat16(v);
    lo = __float2bfloat16(v - __bfloat162float(hi));
}

// ========================= W pre-split kernels (tiny) =========================
__global__ __launch_bounds__(512) void k_wconv(const float* __restrict__ w) {
    int idx = blockIdx.x * 512 + threadIdx.x;     // o*256 + c
    if (idx >= OC3 * CIN) return;
    int o = idx >> 8, c = idx & 255;
    __nv_bfloat16 hi, lo;
    bf16_split(w[idx], hi, lo);
    int mt = o >> 7, m = o & 127, ch = c >> 6, k = c & 63;
    size_t base = ((size_t)((mt * 4 + ch)) * 128 + m) * 64 + k;
    g_w[base]                            = hi;
    g_w[(size_t)3 * 4 * 128 * 64 + base] = lo;
}

__global__ __launch_bounds__(512) void k_wconv2(const float* __restrict__ w) {
    int idx = blockIdx.x * 512 + threadIdx.x;     // o*128 + c
    if (idx >= CIN * HID) return;
    __nv_bfloat16 hi, lo;
    bf16_split(w[idx], hi, lo);
    g_w2[idx]              = hi;
    g_w2[CIN * HID + idx]  = lo;
}

__global__ void k_zero_ctx() {
    g_ctx[blockIdx.x * 1024 + threadIdx.x] = 0.f;
}

// ========================= QKV GEMM on mma.sync (HMMA) =========================
// 128 threads, 4 warps (2m x 2n), warp tile 64x64, CTA tile 128m x 128n.
// 2 CTAs/SM. R10/R13 structure + fused k-softmax partials in epilogue (mt==1).
#define QKV_SMEM 98304
#define QB_OFF   32768

__global__ __launch_bounds__(128, 2) void k_qkv_mma(const float* __restrict__ x) {
    extern __shared__ __align__(1024) char smem[];
    const uint32_t sb = smem_u32(smem);
    const int mt = blockIdx.x;            // mt adjacent -> X slice L2 reuse
    const int n0 = blockIdx.y * 128;
    const int b  = blockIdx.z;
    const int tid = threadIdx.x, wid = tid >> 5, lane = tid & 31;
    const int warp_m = wid >> 1, warp_n = wid & 1;
    const float* xb = x + (size_t)b * CIN * NTOK + n0;

    float acc[4][8][4];
#pragma unroll
    for (int i = 0; i < 4; i++)
#pragma unroll
        for (int j = 0; j < 8; j++)
#pragma unroll
            for (int r = 0; r < 4; r++) acc[i][j][r] = 0.f;

#define WCP(c) do { \
    _Pragma("unroll") \
    for (int p = 0; p < 2; p++) { \
        const char* srcb = (const char*)g_w + (((size_t)(p * 3 + mt) * 4 + (c))) * 16384; \
        _Pragma("unroll") \
        for (int i = 0; i < 8; i++) { \
            int u = tid + 128 * i;               /* 0..1023 16B units */ \
            int m = u >> 3, ks = u & 7; \
            uint32_t dst = sb + p * 16384 + m * 128 + ((ks * 16) ^ ((m & 7) << 4)); \
            CP_ASYNC16(dst, srcb + (size_t)u * 16); \
        } \
    } \
} while (0)

    float4 xr[8];
#define XLDG(c, hh) do { \
    _Pragma("unroll") \
    for (int i = 0; i < 8; i++) { \
        int r = (hh) * 32 + (tid >> 5) + 4 * i; \
        xr[i] = *(const float4*)&xb[(size_t)((c) * 64 + r) * NTOK + (tid & 31) * 4]; \
    } \
} while (0)

#define XSTS(buf, hh) do { \
    _Pragma("unroll") \
    for (int i = 0; i < 8; i++) { \
        int r = (hh) * 32 + (tid >> 5) + 4 * i; \
        float4 v = xr[i]; \
        __nv_bfloat16 h0, h1, h2, h3, l0, l1, l2, l3; \
        bf16_split(v.x, h0, l0); bf16_split(v.y, h1, l1); \
        bf16_split(v.z, h2, l2); bf16_split(v.w, h3, l3); \
        uint2 hv = make_uint2((uint32_t)__bfloat16_as_ushort(h0) | ((uint32_t)__bfloat16_as_ushort(h1) << 16), \
                              (uint32_t)__bfloat16_as_ushort(h2) | ((uint32_t)__bfloat16_as_ushort(h3) << 16)); \
        uint2 lv = make_uint2((uint32_t)__bfloat16_as_ushort(l0) | ((uint32_t)__bfloat16_as_ushort(l1) << 16), \
                              (uint32_t)__bfloat16_as_ushort(l2) | ((uint32_t)__bfloat16_as_ushort(l3) << 16)); \
        uint32_t off = (uint32_t)r * 256 + ((((uint32_t)(tid & 31)) * 8) ^ (((uint32_t)r & 7) << 4)); \
        *(uint2*)(smem + QB_OFF + (buf) * 32768 + off)         = hv; \
        *(uint2*)(smem + QB_OFF + (buf) * 32768 + 16384 + off) = lv; \
    } \
} while (0)

    const int lm = lane & 15;
    const int khalf = (lane >> 4) << 3;

#define MMATERM(pa, pb, cur) do { \
    const uint32_t abase = sb + (pa) * 16384; \
    const uint32_t bbase = sb + QB_OFF + (cur) * 32768 + (pb) * 16384; \
    _Pragma("unroll") \
    for (int ks = 0; ks < 4; ks++) { \
        uint32_t ar[4][4]; \
        _Pragma("unroll") \
        for (int im = 0; im < 4; im++) { \
            uint32_t m_row = (uint32_t)(warp_m * 64 + im * 16 + lm); \
            uint32_t k_off = (uint32_t)(ks * 16 + khalf); \
            uint32_t addr = abase + m_row * 128 + ((k_off * 2) ^ ((m_row & 7) << 4)); \
            LDSM_X4(ar[im][0], ar[im][1], ar[im][2], ar[im][3], addr); \
        } \
        uint32_t br[4][4]; \
        _Pragma("unroll") \
        for (int jb = 0; jb < 4; jb++) { \
            uint32_t k_row = (uint32_t)(ks * 16 + lm); \
            uint32_t n_off = (uint32_t)(warp_n * 64 + jb * 16 + khalf); \
            uint32_t addr = bbase + k_row * 256 + ((n_off * 2) ^ ((k_row & 7) << 4)); \
            LDSM_X4_T(br[jb][0], br[jb][1], br[jb][2], br[jb][3], addr); \
        } \
        _Pragma("unroll") \
        for (int im = 0; im < 4; im++) { \
            _Pragma("unroll") \
            for (int jb = 0; jb < 4; jb++) { \
                MMA_16816(acc[im][jb * 2 + 0], ar[im], br[jb][0], br[jb][1]); \
                MMA_16816(acc[im][jb * 2 + 1], ar[im], br[jb][2], br[jb][3]); \
            } \
        } \
    } \
} while (0)

    // prologue: chunk 0 (W + both B halves)
    WCP(0);
    CP_COMMIT();
    XLDG(0, 0);
    XSTS(0, 0);
    XLDG(0, 1);
    XSTS(0, 1);
    CP_WAIT0();
    __syncthreads();

    for (int c = 0; c < 4; ++c) {
        const int cur = c & 1, nxt = cur ^ 1;
        if (c < 3) XLDG(c + 1, 0);

        MMATERM(0, 0, cur);          // Ahi x Bhi
        if (c < 3) {
            XSTS(nxt, 0);
            XLDG(c + 1, 1);
        }
        MMATERM(0, 1, cur);          // Ahi x Blo
        MMATERM(1, 0, cur);          // Alo x Bhi  (last A read this chunk)

        __syncthreads();             // all warps done reading A
        if (c < 3) {
            WCP(c + 1);              // overwrite single A buffer
            CP_COMMIT();
            XSTS(nxt, 1);
            CP_WAIT0();
        }
        __syncthreads();
    }

    // ---- epilogue: direct STG ----
    const int g = lane >> 2, tig = lane & 3;
    float* outb = g_qkv + ((size_t)b * OC3 + mt * 128) * NTOK + n0;
#pragma unroll
    for (int im = 0; im < 4; im++) {
        const int row = warp_m * 64 + im * 16 + g;
#pragma unroll
        for (int jg = 0; jg < 8; jg++) {
            const int col = warp_n * 64 + jg * 8 + tig * 2;
            *(float2*)&outb[(size_t)row * NTOK + col] =
                make_float2(acc[im][jg][0], acc[im][jg][1]);
            *(float2*)&outb[(size_t)(row + 8) * NTOK + col] =
                make_float2(acc[im][jg][2], acc[im][jg][3]);
        }
    }

    // ---- fused k-softmax partials (K rows live in mt==1 CTAs) ----
    if (mt == 1) {
        float rm[8], rs[8];
#pragma unroll
        for (int im = 0; im < 4; im++) {
#pragma unroll
            for (int hf = 0; hf < 2; hf++) {
                float m = -1e30f;
#pragma unroll
                for (int jg = 0; jg < 8; jg++)
                    m = fmaxf(m, fmaxf(acc[im][jg][hf * 2 + 0], acc[im][jg][hf * 2 + 1]));
                float s = 0.f;
#pragma unroll
                for (int jg = 0; jg < 8; jg++)
                    s += __expf(acc[im][jg][hf * 2 + 0] - m) +
                         __expf(acc[im][jg][hf * 2 + 1] - m);
                // reduce over the 4 tig lanes (same rows)
#pragma unroll
                for (int d = 1; d < 4; d <<= 1) {
                    float mo = __shfl_xor_sync(0xffffffffu, m, d);
                    float so = __shfl_xor_sync(0xffffffffu, s, d);
                    float M = fmaxf(m, mo);
                    s = s * __expf(m - M) + so * __expf(mo - M);
                    m = M;
                }
                rm[im * 2 + hf] = m;
                rs[im * 2 + hf] = s;
            }
        }
        float* pm = (float*)(smem + QB_OFF);      // B region dead; reuse
        float* ps = pm + 128;
        __syncthreads();
        if (warp_n == 0 && tig == 0) {
#pragma unroll
            for (int im = 0; im < 4; im++) {
                int r0 = warp_m * 64 + im * 16 + g;
                pm[r0]     = rm[im * 2];     ps[r0]     = rs[im * 2];
                pm[r0 + 8] = rm[im * 2 + 1]; ps[r0 + 8] = rs[im * 2 + 1];
            }
        }
        __syncthreads();
        if (warp_n == 1 && tig == 0) {
#pragma unroll
            for (int im = 0; im < 4; im++) {
#pragma unroll
                for (int hf = 0; hf < 2; hf++) {
                    int r0 = warp_m * 64 + im * 16 + g + hf * 8;
                    float m1 = pm[r0], s1 = ps[r0];
                    float m2 = rm[im * 2 + hf], s2 = rs[im * 2 + hf];
                    float M = fmaxf(m1, m2);
                    float S = s1 * __expf(m1 - M) + s2 * __expf(m2 - M);
                    g_kpart[(size_t)(b * 128 + r0) * 256 + blockIdx.y] = make_float2(M, S);
                }
            }
        }
    }
#undef WCP
#undef XLDG
#undef XSTS
#undef MMATERM
}

// =====================================================================
// Kernel 2: combine 256 per-tile (max, sumexp) partials per K row.
// =====================================================================
__global__ __launch_bounds__(256) void k_kcomb() {
    const int row = blockIdx.x;          // 0..511
    const int tid = threadIdx.x;
    __shared__ float sm[8], ss[8];
    float2 v = g_kpart[(size_t)row * 256 + tid];
    float m = v.x, s = v.y;
#pragma unroll
    for (int d = 16; d > 0; d >>= 1) {
        float mo = __shfl_xor_sync(0xffffffffu, m, d);
        float so = __shfl_xor_sync(0xffffffffu, s, d);
        float M = fmaxf(m, mo);
        s = s * __expf(m - M) + so * __expf(mo - M);
        m = M;
    }
    if ((tid & 31) == 0) { sm[tid >> 5] = m; ss[tid >> 5] = s; }
    __syncthreads();
    if (tid < 8) {
        m = sm[tid]; s = ss[tid];
#pragma unroll
        for (int d = 4; d > 0; d >>= 1) {
            float mo = __shfl_xor_sync(0x000000ffu, m, d);
            float so = __shfl_xor_sync(0x000000ffu, s, d);
            float M = fmaxf(m, mo);
            s = s * __expf(m - M) + so * __expf(mo - M);
            m = M;
        }
        if (tid == 0) {
            g_kmax[row]  = m;
            g_krinv[row] = 1.f / s;
        }
    }
}

// =====================================================================
// Kernel 3: context[b,h,d,e] = sum_n softmax_k(d,n) * v(e,n)
// split-K: 32 chunks of 1024 tokens. (R14 row-major version.)
// =====================================================================
__global__ __launch_bounds__(256) void k_context() {
    const int chunk = blockIdx.x;
    const int h = blockIdx.y, b = blockIdx.z;
    const int tid = threadIdx.x;
    const int g = tid >> 6, t = tid & 63;
    const int d0 = (t >> 3) << 2;
    const int e0 = (t & 7) << 2;

    __shared__ float sk[32][65];
    __shared__ float sv[32][65];

    const int lr1 = tid >> 4;
    const int c4  = (tid & 15) << 2;
    const int krow = (b * NHEAD + h) * DHEAD;
    const float km1 = g_kmax[krow + lr1],      ri1 = g_krinv[krow + lr1];
    const float km2 = g_kmax[krow + lr1 + 16], ri2 = g_krinv[krow + lr1 + 16];

    const float* kp = g_qkv + ((size_t)(b * OC3 + HID      + h * DHEAD)) * NTOK;
    const float* vp = g_qkv + ((size_t)(b * OC3 + 2 * HID  + h * DHEAD)) * NTOK;

    float acc[4][4];
#pragma unroll
    for (int i = 0; i < 4; i++)
#pragma unroll
        for (int j = 0; j < 4; j++) acc[i][j] = 0.f;

    const int nchunk0 = chunk * 1024;
    for (int it = 0; it < 16; it++) {
        const int nb = nchunk0 + it * 64;
        float4 kv1 = *(const float4*)&kp[(size_t)lr1 * NTOK + nb + c4];
        float4 kv2 = *(const float4*)&kp[(size_t)(lr1 + 16) * NTOK + nb + c4];
        float4 vv1 = *(const float4*)&vp[(size_t)lr1 * NTOK + nb + c4];
        float4 vv2 = *(const float4*)&vp[(size_t)(lr1 + 16) * NTOK + nb + c4];
        sk[lr1][c4 + 0] = __expf(kv1.x - km1) * ri1;
        sk[lr1][c4 + 1] = __expf(kv1.y - km1) * ri1;
        sk[lr1][c4 + 2] = __expf(kv1.z - km1) * ri1;
        sk[lr1][c4 + 3] = __expf(kv1.w - km1) * ri1;
        sk[lr1 + 16][c4 + 0] = __expf(kv2.x - km2) * ri2;
        sk[lr1 + 16][c4 + 1] = __expf(kv2.y - km2) * ri2;
        sk[lr1 + 16][c4 + 2] = __expf(kv2.z - km2) * ri2;
        sk[lr1 + 16][c4 + 3] = __expf(kv2.w - km2) * ri2;
        sv[lr1][c4 + 0] = vv1.x; sv[lr1][c4 + 1] = vv1.y;
        sv[lr1][c4 + 2] = vv1.z; sv[lr1][c4 + 3] = vv1.w;
        sv[lr1 + 16][c4 + 0] = vv2.x; sv[lr1 + 16][c4 + 1] = vv2.y;
        sv[lr1 + 16][c4 + 2] = vv2.z; sv[lr1 + 16][c4 + 3] = vv2.w;
        __syncthreads();

        const int nnb = g << 4;
#pragma unroll
        for (int s = 0; s < 16; s++) {
            const int nn = nnb + s;
            float ka[4], vb[4];
#pragma unroll
            for (int i = 0; i < 4; i++) ka[i] = sk[d0 + i][nn];
#pragma unroll
            for (int j = 0; j < 4; j++) vb[j] = sv[e0 + j][nn];
#pragma unroll
            for (int i = 0; i < 4; i++)
#pragma unroll
                for (int j = 0; j < 4; j++) acc[i][j] += ka[i] * vb[j];
        }
        __syncthreads();
    }

    float* cp = g_ctx + (size_t)(b * NHEAD + h) * DHEAD * DHEAD;
#pragma unroll
    for (int i = 0; i < 4; i++)
#pragma unroll
        for (int j = 0; j < 4; j++)
            atomicAdd(&cp[(d0 + i) * DHEAD + e0 + j], acc[i][j]);
}

// =====================================================================
// Kernel 4 (fused): q-softmax + att + w_out GEMM (HMMA) + bias + LN.
// R13 structure + Alo prefetched into dead qs region (overlaps Ahi FTERMs).
// =====================================================================
#define FIN_SMEM   219136
#define F_OFF_B    65536
#define F_OFF_QS   131072
#define F_OFF_CTX  198656
#define F_OFF_BIAS 215040
#define F_OFF_GAM  216064
#define F_OFF_BET  217088
#define F_OFF_MEAN 218112
#define F_OFF_STD  218624

__global__ __launch_bounds__(256, 1) void k_final2(const float* __restrict__ bias,
                                                   const float* __restrict__ gamma,
                                                   const float* __restrict__ beta,
                                                   float* __restrict__ out) {
    extern __shared__ __align__(1024) char smem[];
    const uint32_t sb = smem_u32(smem);
    const int b  = blockIdx.y;
    const int n0 = blockIdx.x * 128;
    const int tid = threadIdx.x, wid = tid >> 5, lane = tid & 31;
    const int warp_m = wid >> 1, warp_n = wid & 1;

    float* qs    = (float*)(smem + F_OFF_QS);    // [128][132]
    float* sctx  = (float*)(smem + F_OFF_CTX);   // [4096]
    float* sbias = (float*)(smem + F_OFF_BIAS);
    float* sgam  = (float*)(smem + F_OFF_GAM);
    float* sbet  = (float*)(smem + F_OFF_BET);
    float* smean = (float*)(smem + F_OFF_MEAN);
    float* srstd = (float*)(smem + F_OFF_STD);

    // w_out plane p -> dstbase (4096 16B units, swizzled rows of 256B)
#define WCP2(p, dstbase) do { \
    const char* srcb = (const char*)g_w2 + (size_t)(p) * 65536; \
    _Pragma("unroll") \
    for (int i = 0; i < 16; i++) { \
        int u = tid + 256 * i; \
        int m = u >> 4, ks = u & 15; \
        uint32_t dst = (dstbase) + m * 256 + ((ks * 16) ^ ((m & 7) << 4)); \
        CP_ASYNC16(dst, srcb + (size_t)u * 16); \
    } \
} while (0)

    // ---- 1. async copy: w_out HI plane + ctx + q tile (all overlapped) ----
    WCP2(0, sb);
    {
        const char* csrc = (const char*)(g_ctx + b * 4096);
#pragma unroll
        for (int i = 0; i < 4; i++) {
            int u = tid + 256 * i;               // 0..1023 16B units
            CP_ASYNC16(sb + F_OFF_CTX + u * 16, csrc + (size_t)u * 16);
        }
#pragma unroll
        for (int i = 0; i < 16; i++) {
            int idx = tid + i * 256;             // 0..4095 float4s (128 rows x 32)
            int r = idx >> 5, c4 = (idx & 31) << 2;
            CP_ASYNC16(sb + F_OFF_QS + (uint32_t)(r * 132 + c4) * 4,
                       (const char*)&g_qkv[((size_t)b * OC3 + r) * NTOK + n0 + c4]);
        }
    }
    CP_COMMIT();

    // ---- 2. LN params (small, plain LDG) ----
    if (tid < 64) {
        sbias[tid]       = bias[tid];        sbias[tid + 64]  = bias[tid + 64];
        sbias[tid + 128] = bias[tid + 128];  sbias[tid + 192] = bias[tid + 192];
        sgam[tid]        = gamma[tid];       sgam[tid + 64]   = gamma[tid + 64];
        sgam[tid + 128]  = gamma[tid + 128]; sgam[tid + 192]  = gamma[tid + 192];
        sbet[tid]        = beta[tid];        sbet[tid + 64]   = beta[tid + 64];
        sbet[tid + 128]  = beta[tid + 128];  sbet[tid + 192]  = beta[tid + 192];
    }
    CP_WAIT0();
    __syncthreads();

    // ---- 3. q softmax over d per (h, n): 512 pairs, 2 per thread ----
#pragma unroll
    for (int pp = 0; pp < 2; pp++) {
        const int p = tid + pp * 256;
        const int h = p >> 7, n = p & 127;
        float qv[32];
        float m = -1e30f;
#pragma unroll
        for (int d = 0; d < 32; d++) { qv[d] = qs[(h * 32 + d) * 132 + n]; m = fmaxf(m, qv[d]); }
        float s = 0.f;
#pragma unroll
        for (int d = 0; d < 32; d++) { qv[d] = __expf(qv[d] - m); s += qv[d]; }
        const float r = SCALE / s;
#pragma unroll
        for (int d = 0; d < 32; d++) qs[(h * 32 + d) * 132 + n] = qv[d] * r;
    }
    __syncthreads();

    // ---- 4. att[e, n] = sum_d ctx[h,d,e] * qs[h*32+d][n] (tiled, float4 LDS) ----
    {
        const int e = tid >> 1, nh = tid & 1;    // e 0..127
        const int h = e >> 5, ep = e & 31;
        const float* cb = sctx + h * 1024 + ep;
        char* bhi = smem + F_OFF_B;
        char* blo = bhi + 32768;
#pragma unroll
        for (int half = 0; half < 2; half++) {
            float av[32];
#pragma unroll
            for (int j = 0; j < 32; j++) av[j] = 0.f;
            const float* qb = qs + (h * 32) * 132 + nh * 64 + half * 32;
#pragma unroll
            for (int d = 0; d < 32; d++) {
                const float cv = cb[d * 32];
                const float4* q4 = (const float4*)(qb + d * 132);
#pragma unroll
                for (int j4 = 0; j4 < 8; j4++) {
                    float4 q = q4[j4];
                    av[j4 * 4 + 0] += cv * q.x;
                    av[j4 * 4 + 1] += cv * q.y;
                    av[j4 * 4 + 2] += cv * q.z;
                    av[j4 * 4 + 3] += cv * q.w;
                }
            }
#pragma unroll
            for (int t = 0; t < 16; t++) {
                __nv_bfloat16 h0, h1, l0, l1;
                bf16_split(av[2 * t],     h0, l0);
                bf16_split(av[2 * t + 1], h1, l1);
                uint32_t hv = (uint32_t)__bfloat16_as_ushort(h0) | ((uint32_t)__bfloat16_as_ushort(h1) << 16);
                uint32_t lv = (uint32_t)__bfloat16_as_ushort(l0) | ((uint32_t)__bfloat16_as_ushort(l1) << 16);
                uint32_t off = (uint32_t)e * 256 +
                    (((uint32_t)(nh * 128 + half * 64 + 4 * t)) ^ (((uint32_t)e & 7) << 4));
                *(uint32_t*)(bhi + off) = hv;
                *(uint32_t*)(blo + off) = lv;
            }
        }
    }
    __syncthreads();    // qs region now dead (att consumed it)

    // ---- 5. MMA. Alo prefetched into dead qs region, overlapping Ahi FTERMs.
    float acc[4][8][4];
#pragma unroll
    for (int i = 0; i < 4; i++)
#pragma unroll
        for (int j = 0; j < 8; j++)
#pragma unroll
            for (int r = 0; r < 4; r++) acc[i][j][r] = 0.f;

    const int lm = lane & 15;
    const int khalf = (lane >> 4) << 3;

#define FTERM(ab, pb) do { \
    const uint32_t bbase = sb + F_OFF_B + (pb) * 32768; \
    _Pragma("unroll") \
    for (int ks = 0; ks < 8; ks++) { \
        uint32_t ar[4][4]; \
        _Pragma("unroll") \
        for (int im = 0; im < 4; im++) { \
            uint32_t m_row = (uint32_t)(warp_m * 64 + im * 16 + lm); \
            uint32_t k_off = (uint32_t)(ks * 16 + khalf); \
            uint32_t addr = (ab) + m_row * 256 + ((k_off * 2) ^ ((m_row & 7) << 4)); \
            LDSM_X4(ar[im][0], ar[im][1], ar[im][2], ar[im][3], addr); \
        } \
        uint32_t br[4][4]; \
        _Pragma("unroll") \
        for (int jb = 0; jb < 4; jb++) { \
            uint32_t k_row = (uint32_t)(ks * 16 + lm); \
            uint32_t n_off = (uint32_t)(warp_n * 64 + jb * 16 + khalf); \
            uint32_t addr = bbase + k_row * 256 + ((n_off * 2) ^ ((k_row & 7) << 4)); \
            LDSM_X4_T(br[jb][0], br[jb][1], br[jb][2], br[jb][3], addr); \
        } \
        _Pragma("unroll") \
        for (int im = 0; im < 4; im++) { \
            _Pragma("unroll") \
            for (int jb = 0; jb < 4; jb++) { \
                MMA_16816(acc[im][jb * 2 + 0], ar[im], br[jb][0], br[jb][1]); \
                MMA_16816(acc[im][jb * 2 + 1], ar[im], br[jb][2], br[jb][3]); \
            } \
        } \
    } \
} while (0)

    WCP2(1, sb + F_OFF_QS);   // Alo -> dead qs region (async, overlaps FTERMs)
    CP_COMMIT();
    FTERM(sb, 0);             // Ahi x Bhi
    FTERM(sb, 1);             // Ahi x Blo
    CP_WAIT0();
    __syncthreads();          // make Alo visible to all warps
    FTERM(sb + F_OFF_QS, 0);  // Alo x Bhi
    __syncthreads();          // A/B/qs regions dead; reuse as stage

    // ---- 6. stage[256][132] = acc + bias ----
    float* stage = (float*)smem;
    {
        const int g = lane >> 2, tig = lane & 3;
#pragma unroll
        for (int im = 0; im < 4; im++) {
            const int row = warp_m * 64 + im * 16 + g;
            const float b0 = sbias[row], b1 = sbias[row + 8];
#pragma unroll
            for (int jg = 0; jg < 8; jg++) {
                const int col = warp_n * 64 + jg * 8 + tig * 2;
                *(float2*)&stage[row * 132 + col] =
                    make_float2(acc[im][jg][0] + b0, acc[im][jg][1] + b0);
                *(float2*)&stage[(row + 8) * 132 + col] =
                    make_float2(acc[im][jg][2] + b1, acc[im][jg][3] + b1);
            }
        }
    }
    __syncthreads();

    // ---- 7. LN stats: 2 threads per token ----
    {
        const int t = tid >> 1, part = tid & 1;
        float sum = 0.f, sq = 0.f;
#pragma unroll
        for (int jj = 0; jj < 128; jj++) {
            const float v = stage[(part + jj * 2) * 132 + t];
            sum += v; sq += v * v;
        }
        sum += __shfl_xor_sync(0xffffffffu, sum, 1);
        sq  += __shfl_xor_sync(0xffffffffu, sq, 1);
        const float mean = sum * (1.f / 256.f);
        const float var  = sq * (1.f / 256.f) - mean * mean;
        if (part == 0) {
            smean[t] = mean;
            srstd[t] = rsqrtf(var + LN_EPS);
        }
    }
    __syncthreads();

    // ---- 8. normalized write-out (8192 float4s) ----
    float* outb = out + (size_t)b * CIN * NTOK + n0;
#pragma unroll
    for (int it = 0; it < 32; it++) {
        int idx = it * 256 + tid;
        int o = idx >> 5, q = (idx & 31) << 2;
        const float gm = sgam[o], bt = sbet[o];
        float4 v = *(float4*)&stage[o * 132 + q];
        v.x = (v.x - smean[q + 0]) * srstd[q + 0] * gm + bt;
        v.y = (v.y - smean[q + 1]) * srstd[q + 1] * gm + bt;
        v.z = (v.z - smean[q + 2]) * srstd[q + 2] * gm + bt;
        v.w = (v.w - smean[q + 3]) * srstd[q + 3] * gm + bt;
        *(float4*)&outb[(size_t)o * NTOK + q] = v;
    }
#undef WCP2
#undef FTERM
}

// =====================================================================
extern "C" void kernel_launch(void* const* d_in, const int* in_sizes, int n_in,
                              void* d_out, int out_size) {
    const float* x      = (const float*)d_in[0];
    const float* w_qkv  = (const float*)d_in[1];
    const float* w_out  = (const float*)d_in[2];
    const float* bias   = (const float*)d_in[3];
    const float* gamma  = (const float*)d_in[4];
    const float* beta   = (const float*)d_in[5];
    float* out = (float*)d_out;

    cudaFuncSetAttribute(k_qkv_mma, cudaFuncAttributeMaxDynamicSharedMemorySize,
                         QKV_SMEM);
    cudaFuncSetAttribute(k_final2, cudaFuncAttributeMaxDynamicSharedMemorySize,
                         FIN_SMEM);

    // k_qkv_mma stays at launch index 3 (the one ncu profiles).
    k_wconv<<<192, 512>>>(w_qkv);                                   // 0
    k_wconv2<<<64, 512>>>(w_out);                                   // 1
    k_zero_ctx<<<16, 1024>>>();                                     // 2
    k_qkv_mma<<<dim3(3, NTOK / 128, BATCH), 128, QKV_SMEM>>>(x);    // 3 <- profiled
    k_kcomb<<<512, 256>>>();                                        // 4
    k_context<<<dim3(32, NHEAD, BATCH), 256>>>();                   // 5
    k_final2<<<dim3(NTOK / 128, BATCH), 256, FIN_SMEM>>>(bias, gamma, beta, out); // 6
}